// round 14
// baseline (speedup 1.0000x reference)
#include <cuda_runtime.h>
#include <cuda_bf16.h>

// Problem constants
#define BATCH 4096
#define SEQ   512
#define HID   32
#define NB    4            // batch elements per warp; 1024 one-warp blocks

using u64 = unsigned long long;

// ---- packed f32x2 helpers (FFMA2 path, PTX-only) ----
__device__ __forceinline__ u64 pack2(float lo, float hi) {
    u64 r; asm("mov.b64 %0, {%1, %2};" : "=l"(r) : "f"(lo), "f"(hi)); return r;
}
__device__ __forceinline__ void unpack2(u64 v, float& lo, float& hi) {
    asm("mov.b64 {%0, %1}, %2;" : "=f"(lo), "=f"(hi) : "l"(v));
}
__device__ __forceinline__ u64 fma2(u64 a, u64 b, u64 c) {
    u64 d; asm("fma.rn.f32x2 %0, %1, %2, %3;" : "=l"(d) : "l"(a), "l"(b), "l"(c)); return d;
}
__device__ __forceinline__ float lo2(u64 v) {
    float lo, hi; unpack2(v, lo, hi); return lo;
}

// ---- hardware tanh (MUFU.TANH, sm_75+) ----
__device__ __forceinline__ float tanh_hw(float v) {
    float r; asm("tanh.approx.f32 %0, %1;" : "=f"(r) : "f"(v)); return r;
}

// ---- exact-path activations for the tail section (unchanged precision) ----
__device__ __forceinline__ float sigf(float v) {
    return __fdividef(1.0f, 1.0f + __expf(-v));
}
__device__ __forceinline__ float tanhf_fast(float v) {
    return __fdividef(2.0f, 1.0f + __expf(-2.0f * v)) - 1.0f;
}

// ---------------------------------------------------------------------------
// Single fused kernel: inline weight pack -> 512-step scan -> cell2 + FC.
// 1024 one-warp blocks; lane = hidden unit j; NB=4 batches per warp split
// into two phase-shifted groups of 2 (A and B, separate Hs buffers).
// Loop body: epiB(t-1) || matvecA(t) -> sync -> epiA(t) || matvecB(t) -> sync.
// Each group's serial epilogue/store/turnaround overlaps the other group's
// independent FFMA2 stream, moving work across the old sync boundary.
// ---------------------------------------------------------------------------
__global__ void __launch_bounds__(32) lstm_kernel(
    const float* __restrict__ x,
    const float* __restrict__ h0,   const float* __restrict__ c0,
    const float* __restrict__ Wih1, const float* __restrict__ Whh1,
    const float* __restrict__ bih1, const float* __restrict__ bhh1,
    const float* __restrict__ Wih2, const float* __restrict__ Whh2,
    const float* __restrict__ bih2, const float* __restrict__ bhh2,
    const float* __restrict__ Wfc,  const float* __restrict__ bfc,
    float* __restrict__ out)
{
    __shared__ ulonglong2 HsA[2][32];    // group A: [buf][k] = ((hA0,hA0),(hA1,hA1))
    __shared__ ulonglong2 HsB[2][32];    // group B

    const int j  = threadIdx.x;          // lane = hidden unit
    const int b0 = blockIdx.x * NB;

    // ---- inline pack: all 32 k-slices of scaled Whh1 into registers ----
    // i,f,o rows scaled by 0.5 (sigmoid-as-tanh form); g row unscaled.
    u64 wIFr[32], wGOr[32];
    {
        const float4* W1v = reinterpret_cast<const float4*>(Whh1);
        #pragma unroll
        for (int q = 0; q < 8; q++) {
            float4 wi = W1v[(0  + j) * 8 + q];
            float4 wf = W1v[(32 + j) * 8 + q];
            float4 wg = W1v[(64 + j) * 8 + q];
            float4 wo = W1v[(96 + j) * 8 + q];
            wIFr[4 * q + 0] = pack2(0.5f * wi.x, 0.5f * wf.x);
            wIFr[4 * q + 1] = pack2(0.5f * wi.y, 0.5f * wf.y);
            wIFr[4 * q + 2] = pack2(0.5f * wi.z, 0.5f * wf.z);
            wIFr[4 * q + 3] = pack2(0.5f * wi.w, 0.5f * wf.w);
            wGOr[4 * q + 0] = pack2(wg.x, 0.5f * wo.x);
            wGOr[4 * q + 1] = pack2(wg.y, 0.5f * wo.y);
            wGOr[4 * q + 2] = pack2(wg.z, 0.5f * wo.z);
            wGOr[4 * q + 3] = pack2(wg.w, 0.5f * wo.w);
        }
    }

    // Per-lane constants: combined bias and input weight, gate-paired, scaled
    const u64 biasIF = pack2(0.5f * (bih1[0  + j] + bhh1[0  + j]),
                             0.5f * (bih1[32 + j] + bhh1[32 + j]));
    const u64 biasGO = pack2(       (bih1[64 + j] + bhh1[64 + j]),
                             0.5f * (bih1[96 + j] + bhh1[96 + j]));
    const u64 wihIF  = pack2(0.5f * Wih1[0  + j],
                             0.5f * Wih1[32 + j]);
    const u64 wihGO  = pack2(       Wih1[64 + j],
                             0.5f * Wih1[96 + j]);

    // Carry c in registers; h lives in the smem stages
    float cA0 = c0[(b0 + 0) * HID + j];
    float cA1 = c0[(b0 + 1) * HID + j];
    float cB0 = c0[(b0 + 2) * HID + j];
    float cB1 = c0[(b0 + 3) * HID + j];

    {
        float a0 = h0[(b0 + 0) * HID + j];
        float a1 = h0[(b0 + 1) * HID + j];
        float b0_ = h0[(b0 + 2) * HID + j];
        float b1_ = h0[(b0 + 3) * HID + j];
        ulonglong2 hq;
        hq.x = pack2(a0, a0);  hq.y = pack2(a1, a1);  HsA[0][j] = hq;
        hq.x = pack2(b0_, b0_); hq.y = pack2(b1_, b1_); HsB[0][j] = hq;
    }

    // x[t][b0..b0+3] contiguous: uniform LDG.128 broadcast; prefetch 1 ahead
    float4 xc = *reinterpret_cast<const float4*>(&x[b0]);
    __syncwarp();

    // matvec for one 2-batch group: per k, 1 broadcast LDS.128 + 4 FFMA2.
    auto matvec2 = [&](const ulonglong2 (&H)[32], float x0, float x1,
                       u64& aIF0, u64& aGO0, u64& aIF1, u64& aGO1) {
        u64 xd0 = pack2(x0, x0);
        u64 xd1 = pack2(x1, x1);
        aIF0 = fma2(xd0, wihIF, biasIF);  aGO0 = fma2(xd0, wihGO, biasGO);
        aIF1 = fma2(xd1, wihIF, biasIF);  aGO1 = fma2(xd1, wihGO, biasGO);
        #pragma unroll
        for (int k = 0; k < 32; k++) {
            ulonglong2 hq = H[k];
            u64 wIF = wIFr[k];
            u64 wGO = wGOr[k];
            aIF0 = fma2(hq.x, wIF, aIF0);
            aGO0 = fma2(hq.x, wGO, aGO0);
            aIF1 = fma2(hq.y, wIF, aIF1);
            aGO1 = fma2(hq.y, wGO, aGO1);
        }
    };

    // epilogue for one 2-batch group (MUFU.TANH path)
    auto epi2 = [&](u64 aIF0, u64 aGO0, u64 aIF1, u64 aGO1,
                    float& cc0, float& cc1, float& hn0, float& hn1) {
        float ai0, af0, ag0, ao0, ai1, af1, ag1, ao1;
        unpack2(aIF0, ai0, af0);  unpack2(aGO0, ag0, ao0);
        unpack2(aIF1, ai1, af1);  unpack2(aGO1, ag1, ao1);
        float tg0 = tanh_hw(ag0), tg1 = tanh_hw(ag1);
        float ti0 = tanh_hw(ai0), ti1 = tanh_hw(ai1);
        float tf0 = tanh_hw(af0), tf1 = tanh_hw(af1);
        float to0 = tanh_hw(ao0), to1 = tanh_hw(ao1);
        float ig0 = fmaf(0.5f, ti0, 0.5f), ig1 = fmaf(0.5f, ti1, 0.5f);
        float fg0 = fmaf(0.5f, tf0, 0.5f), fg1 = fmaf(0.5f, tf1, 0.5f);
        float og0 = fmaf(0.5f, to0, 0.5f), og1 = fmaf(0.5f, to1, 0.5f);
        cc0 = fmaf(fg0, cc0, ig0 * tg0);
        cc1 = fmaf(fg1, cc1, ig1 * tg1);
        hn0 = og0 * tanh_hw(cc0);
        hn1 = og1 * tanh_hw(cc1);
    };

    u64 aIFA0, aGOA0, aIFA1, aGOA1;     // group A accumulators
    u64 aIFB0, aGOB0, aIFB1, aGOB1;     // group B accumulators (carried)
    float hnA0, hnA1, hnB0, hnB1;

    // ---------------- peel t = 0 ----------------
    {
        matvec2(HsA[0], xc.x, xc.y, aIFA0, aGOA0, aIFA1, aGOA1);
        epi2(aIFA0, aGOA0, aIFA1, aGOA1, cA0, cA1, hnA0, hnA1);
        {
            ulonglong2 hq;
            hq.x = pack2(hnA0, hnA0); hq.y = pack2(hnA1, hnA1);
            HsA[1][j] = hq;
        }
        matvec2(HsB[0], xc.z, xc.w, aIFB0, aGOB0, aIFB1, aGOB1);
        __syncwarp();
        xc = *reinterpret_cast<const float4*>(&x[1 * BATCH + b0]);
    }

    // ---------------- steady loop t = 1..511 ----------------
    #pragma unroll 1
    for (int t = 1; t < SEQ; t++) {
        const int rb = t & 1;

        const int tn = (t + 1 < SEQ) ? (t + 1) : t;
        float4 xn = *reinterpret_cast<const float4*>(&x[tn * BATCH + b0]);

        // group B epilogue for step t-1 (overlaps matvecA's FFMA2 stream)
        epi2(aIFB0, aGOB0, aIFB1, aGOB1, cB0, cB1, hnB0, hnB1);
        {
            ulonglong2 hq;
            hq.x = pack2(hnB0, hnB0); hq.y = pack2(hnB1, hnB1);
            HsB[rb][j] = hq;
        }

        // group A matvec step t (reads HsA[rb], stored last iteration)
        matvec2(HsA[rb], xc.x, xc.y, aIFA0, aGOA0, aIFA1, aGOA1);
        __syncwarp();          // HsB[rb] visible

        // group A epilogue step t (overlaps matvecB's FFMA2 stream)
        epi2(aIFA0, aGOA0, aIFA1, aGOA1, cA0, cA1, hnA0, hnA1);
        {
            ulonglong2 hq;
            hq.x = pack2(hnA0, hnA0); hq.y = pack2(hnA1, hnA1);
            HsA[rb ^ 1][j] = hq;
        }

        // group B matvec step t (reads HsB[rb], stored this iteration)
        matvec2(HsB[rb], xc.z, xc.w, aIFB0, aGOB0, aIFB1, aGOB1);
        __syncwarp();          // HsA[rb^1] visible next iteration

        xc = xn;
    }

    // final group B epilogue for t = 511
    epi2(aIFB0, aGOB0, aIFB1, aGOB1, cB0, cB1, hnB0, hnB1);
    {
        ulonglong2 hq;
        hq.x = pack2(hnB0, hnB0); hq.y = pack2(hnB1, hnB1);
        HsB[0][j] = hq;        // (512 & 1) = 0
    }
    __syncwarp();
    // A's final h is in HsA[0] (epiA at t=511 wrote rb^1 = 0); B's in HsB[0].

    // ---------------- inline tail: cell 2 + FC (exact path) ----------------
    float c[NB] = { cA0, cA1, cB0, cB1 };
    float a2i[NB], a2f[NB], a2g[NB], a2o[NB];
    {
        float bi2 = bih2[0  + j] + bhh2[0  + j];
        float bf2 = bih2[32 + j] + bhh2[32 + j];
        float bg2 = bih2[64 + j] + bhh2[64 + j];
        float bo2 = bih2[96 + j] + bhh2[96 + j];
        #pragma unroll
        for (int b = 0; b < NB; b++) {
            a2i[b] = bi2; a2f[b] = bf2; a2g[b] = bg2; a2o[b] = bo2;
        }
    }
    {
        const float4* Wi2v = reinterpret_cast<const float4*>(Wih2);
        const float4* Wh2v = reinterpret_cast<const float4*>(Whh2);
        #pragma unroll
        for (int q = 0; q < 8; q++) {
            float4 wi = Wi2v[(0  + j) * 8 + q], hi_ = Wh2v[(0  + j) * 8 + q];
            float4 wf = Wi2v[(32 + j) * 8 + q], hf_ = Wh2v[(32 + j) * 8 + q];
            float4 wg = Wi2v[(64 + j) * 8 + q], hg_ = Wh2v[(64 + j) * 8 + q];
            float4 wo = Wi2v[(96 + j) * 8 + q], ho_ = Wh2v[(96 + j) * 8 + q];
            float ci2[4] = { wi.x + hi_.x, wi.y + hi_.y, wi.z + hi_.z, wi.w + hi_.w };
            float cf2[4] = { wf.x + hf_.x, wf.y + hf_.y, wf.z + hf_.z, wf.w + hf_.w };
            float cg2[4] = { wg.x + hg_.x, wg.y + hg_.y, wg.z + hg_.z, wg.w + hg_.w };
            float co2[4] = { wo.x + ho_.x, wo.y + ho_.y, wo.z + ho_.z, wo.w + ho_.w };
            #pragma unroll
            for (int kk = 0; kk < 4; kk++) {
                int k = 4 * q + kk;
                ulonglong2 hqA = HsA[0][k];
                ulonglong2 hqB = HsB[0][k];
                float hk[NB] = { lo2(hqA.x), lo2(hqA.y), lo2(hqB.x), lo2(hqB.y) };
                #pragma unroll
                for (int b = 0; b < NB; b++) {
                    a2i[b] = fmaf(hk[b], ci2[kk], a2i[b]);
                    a2f[b] = fmaf(hk[b], cf2[kk], a2f[b]);
                    a2g[b] = fmaf(hk[b], cg2[kk], a2g[b]);
                    a2o[b] = fmaf(hk[b], co2[kk], a2o[b]);
                }
            }
        }
    }

    const float wfc_j = Wfc[j];
    const float bfc0  = bfc[0];
    #pragma unroll
    for (int b = 0; b < NB; b++) {
        float cn  = fmaf(sigf(a2f[b]), c[b], sigf(a2i[b]) * tanhf_fast(a2g[b]));
        float h1f = sigf(a2o[b]) * tanhf_fast(cn);
        float v = h1f * wfc_j;
        #pragma unroll
        for (int m = 16; m > 0; m >>= 1)
            v += __shfl_xor_sync(0xffffffffu, v, m);
        if (j == 0) out[b0 + b] = v + bfc0;
    }
}

// ---------------------------------------------------------------------------
// kernel_launch: single fused launch (graph-capturable)
// Input order: x,h0,c0,h1,c1,Wih1,Whh1,bih1,bhh1,Wih2,Whh2,bih2,bhh2,Wfc,bfc
// ---------------------------------------------------------------------------
extern "C" void kernel_launch(void* const* d_in, const int* in_sizes, int n_in,
                              void* d_out, int out_size)
{
    const float* x    = (const float*)d_in[0];
    const float* h0   = (const float*)d_in[1];
    const float* c0   = (const float*)d_in[2];
    const float* Wih1 = (const float*)d_in[5];
    const float* Whh1 = (const float*)d_in[6];
    const float* bih1 = (const float*)d_in[7];
    const float* bhh1 = (const float*)d_in[8];
    const float* Wih2 = (const float*)d_in[9];
    const float* Whh2 = (const float*)d_in[10];
    const float* bih2 = (const float*)d_in[11];
    const float* bhh2 = (const float*)d_in[12];
    const float* Wfc  = (const float*)d_in[13];
    const float* bfc  = (const float*)d_in[14];
    float* out = (float*)d_out;

    lstm_kernel<<<BATCH / NB, 32>>>(x, h0, c0, Wih1, Whh1, bih1, bhh1,
                                    Wih2, Whh2, bih2, bhh2, Wfc, bfc, out);
}

// round 15
// speedup vs baseline: 1.2760x; 1.2760x over previous
#include <cuda_runtime.h>
#include <cuda_bf16.h>

// Problem constants
#define BATCH 4096
#define SEQ   512
#define HID   32
#define NB7   7            // batches per warp (main blocks); 585*7 + 1 = 4096
#define NBLK7 585

using u64 = unsigned long long;

// ---- packed f32x2 helpers (FFMA2 path, PTX-only) ----
__device__ __forceinline__ u64 pack2(float lo, float hi) {
    u64 r; asm("mov.b64 %0, {%1, %2};" : "=l"(r) : "f"(lo), "f"(hi)); return r;
}
__device__ __forceinline__ void unpack2(u64 v, float& lo, float& hi) {
    asm("mov.b64 {%0, %1}, %2;" : "=f"(lo), "=f"(hi) : "l"(v));
}
__device__ __forceinline__ u64 fma2(u64 a, u64 b, u64 c) {
    u64 d; asm("fma.rn.f32x2 %0, %1, %2, %3;" : "=l"(d) : "l"(a), "l"(b), "l"(c)); return d;
}
__device__ __forceinline__ float lo2(u64 v) {
    float lo, hi; unpack2(v, lo, hi); return lo;
}

// ---- hardware tanh (MUFU.TANH, sm_75+) ----
__device__ __forceinline__ float tanh_hw(float v) {
    float r; asm("tanh.approx.f32 %0, %1;" : "=f"(r) : "f"(v)); return r;
}

// ---- exact-path activations for the tail section (unchanged precision) ----
__device__ __forceinline__ float sigf(float v) {
    return __fdividef(1.0f, 1.0f + __expf(-v));
}
__device__ __forceinline__ float tanhf_fast(float v) {
    return __fdividef(2.0f, 1.0f + __expf(-2.0f * v)) - 1.0f;
}

// ---------------------------------------------------------------------------
// Templated body: one warp scans NBT batches [b0, b0+NBT) through all 512
// steps, then runs cell2 + FC for them. Lane = hidden unit j. All Whh1
// weights in registers, scaled so i,f,o gates produce a/2 (sigmoid-as-tanh)
// and g produces a. Hs layout [buf][batch][k] (duplicated-pair u64s):
// conflict-free STS.64 stores, k-paired broadcast LDS.128 loads.
// ---------------------------------------------------------------------------
template <int NBT>
__device__ __forceinline__ void lstm_body(
    int b0, u64 (*Hs)[NB7][HID],                 // shared [2][NB7][32]
    const float* __restrict__ x,
    const float* __restrict__ h0,   const float* __restrict__ c0,
    const float* __restrict__ Wih1, const float* __restrict__ Whh1,
    const float* __restrict__ bih1, const float* __restrict__ bhh1,
    const float* __restrict__ Wih2, const float* __restrict__ Whh2,
    const float* __restrict__ bih2, const float* __restrict__ bhh2,
    const float* __restrict__ Wfc,  const float* __restrict__ bfc,
    float* __restrict__ out)
{
    const int j = threadIdx.x;           // lane = hidden unit

    // ---- inline pack: all 32 k-slices of scaled Whh1 into registers ----
    u64 wIFr[32], wGOr[32];
    {
        const float4* W1v = reinterpret_cast<const float4*>(Whh1);
        #pragma unroll
        for (int q = 0; q < 8; q++) {
            float4 wi = W1v[(0  + j) * 8 + q];
            float4 wf = W1v[(32 + j) * 8 + q];
            float4 wg = W1v[(64 + j) * 8 + q];
            float4 wo = W1v[(96 + j) * 8 + q];
            wIFr[4 * q + 0] = pack2(0.5f * wi.x, 0.5f * wf.x);
            wIFr[4 * q + 1] = pack2(0.5f * wi.y, 0.5f * wf.y);
            wIFr[4 * q + 2] = pack2(0.5f * wi.z, 0.5f * wf.z);
            wIFr[4 * q + 3] = pack2(0.5f * wi.w, 0.5f * wf.w);
            wGOr[4 * q + 0] = pack2(wg.x, 0.5f * wo.x);
            wGOr[4 * q + 1] = pack2(wg.y, 0.5f * wo.y);
            wGOr[4 * q + 2] = pack2(wg.z, 0.5f * wo.z);
            wGOr[4 * q + 3] = pack2(wg.w, 0.5f * wo.w);
        }
    }

    const u64 biasIF = pack2(0.5f * (bih1[0  + j] + bhh1[0  + j]),
                             0.5f * (bih1[32 + j] + bhh1[32 + j]));
    const u64 biasGO = pack2(       (bih1[64 + j] + bhh1[64 + j]),
                             0.5f * (bih1[96 + j] + bhh1[96 + j]));
    const u64 wihIF  = pack2(0.5f * Wih1[0  + j],
                             0.5f * Wih1[32 + j]);
    const u64 wihGO  = pack2(       Wih1[64 + j],
                             0.5f * Wih1[96 + j]);

    float c[NBT];
    #pragma unroll
    for (int b = 0; b < NBT; b++) c[b] = c0[(b0 + b) * HID + j];

    #pragma unroll
    for (int b = 0; b < NBT; b++) {
        float h = h0[(b0 + b) * HID + j];
        Hs[0][b][j] = pack2(h, h);
    }

    // lanes 0..NBT-1 hold x[t][b0+lane]; prefetch one step ahead
    float xc = (j < NBT) ? x[b0 + j] : 0.0f;
    __syncwarp();

    // ---------------- 512-step recurrence ----------------
    #pragma unroll 1
    for (int t = 0; t < SEQ; t++) {
        const int rb = t & 1;

        const int tn = (t + 1 < SEQ) ? (t + 1) : t;
        float xn = (j < NBT) ? x[tn * BATCH + b0 + j] : 0.0f;

        u64 aIF[NBT], aGO[NBT];
        #pragma unroll
        for (int b = 0; b < NBT; b++) {
            float xb = __shfl_sync(0xffffffffu, xc, b);
            u64 xd = pack2(xb, xb);
            aIF[b] = fma2(xd, wihIF, biasIF);
            aGO[b] = fma2(xd, wihGO, biasGO);
        }

        // matvec over k-pairs: per pair, NBT broadcast LDS.128 + 4*NBT FFMA2
        #pragma unroll
        for (int kp = 0; kp < 16; kp++) {
            ulonglong2 hq[NBT];
            #pragma unroll
            for (int b = 0; b < NBT; b++)
                hq[b] = *reinterpret_cast<const ulonglong2*>(&Hs[rb][b][2 * kp]);
            u64 wIF0 = wIFr[2 * kp],     wGO0 = wGOr[2 * kp];
            u64 wIF1 = wIFr[2 * kp + 1], wGO1 = wGOr[2 * kp + 1];
            #pragma unroll
            for (int b = 0; b < NBT; b++) {
                aIF[b] = fma2(hq[b].x, wIF0, aIF[b]);
                aGO[b] = fma2(hq[b].x, wGO0, aGO[b]);
                aIF[b] = fma2(hq[b].y, wIF1, aIF[b]);
                aGO[b] = fma2(hq[b].y, wGO1, aGO[b]);
            }
        }

        // ---- gate-major epilogue (MUFU.TANH) ----
        float ai[NBT], af[NBT], ag[NBT], ao[NBT];
        #pragma unroll
        for (int b = 0; b < NBT; b++) {
            unpack2(aIF[b], ai[b], af[b]);   // pre-halved
            unpack2(aGO[b], ag[b], ao[b]);   // ag full, ao pre-halved
        }
        float tg[NBT], ti[NBT], tf_[NBT], to_[NBT];
        #pragma unroll
        for (int b = 0; b < NBT; b++) tg[b]  = tanh_hw(ag[b]);
        #pragma unroll
        for (int b = 0; b < NBT; b++) ti[b]  = tanh_hw(ai[b]);
        #pragma unroll
        for (int b = 0; b < NBT; b++) tf_[b] = tanh_hw(af[b]);
        #pragma unroll
        for (int b = 0; b < NBT; b++) to_[b] = tanh_hw(ao[b]);

        #pragma unroll
        for (int b = 0; b < NBT; b++) {
            float ig = fmaf(0.5f, ti[b],  0.5f);
            float fg = fmaf(0.5f, tf_[b], 0.5f);
            float og = fmaf(0.5f, to_[b], 0.5f);
            c[b] = fmaf(fg, c[b], ig * tg[b]);
            float hn = og * tanh_hw(c[b]);
            Hs[rb ^ 1][b][j] = pack2(hn, hn);   // stride-8B, conflict-free
        }
        xc = xn;
        __syncwarp();
    }

    // ---------------- inline tail: cell 2 + FC (exact path) ----------------
    // SEQ even -> final h is in Hs[0]; c[] holds final cell state.
    float a2i[NBT], a2f[NBT], a2g[NBT], a2o[NBT];
    {
        float bi2 = bih2[0  + j] + bhh2[0  + j];
        float bf2 = bih2[32 + j] + bhh2[32 + j];
        float bg2 = bih2[64 + j] + bhh2[64 + j];
        float bo2 = bih2[96 + j] + bhh2[96 + j];
        #pragma unroll
        for (int b = 0; b < NBT; b++) {
            a2i[b] = bi2; a2f[b] = bf2; a2g[b] = bg2; a2o[b] = bo2;
        }
    }
    {
        const float4* Wi2v = reinterpret_cast<const float4*>(Wih2);
        const float4* Wh2v = reinterpret_cast<const float4*>(Whh2);
        #pragma unroll
        for (int q = 0; q < 8; q++) {
            float4 wi = Wi2v[(0  + j) * 8 + q], hi_ = Wh2v[(0  + j) * 8 + q];
            float4 wf = Wi2v[(32 + j) * 8 + q], hf_ = Wh2v[(32 + j) * 8 + q];
            float4 wg = Wi2v[(64 + j) * 8 + q], hg_ = Wh2v[(64 + j) * 8 + q];
            float4 wo = Wi2v[(96 + j) * 8 + q], ho_ = Wh2v[(96 + j) * 8 + q];
            float ci2[4] = { wi.x + hi_.x, wi.y + hi_.y, wi.z + hi_.z, wi.w + hi_.w };
            float cf2[4] = { wf.x + hf_.x, wf.y + hf_.y, wf.z + hf_.z, wf.w + hf_.w };
            float cg2[4] = { wg.x + hg_.x, wg.y + hg_.y, wg.z + hg_.z, wg.w + hg_.w };
            float co2[4] = { wo.x + ho_.x, wo.y + ho_.y, wo.z + ho_.z, wo.w + ho_.w };
            #pragma unroll
            for (int kk = 0; kk < 4; kk++) {
                int k = 4 * q + kk;
                #pragma unroll
                for (int b = 0; b < NBT; b++) {
                    float hk = lo2(Hs[0][b][k]);
                    a2i[b] = fmaf(hk, ci2[kk], a2i[b]);
                    a2f[b] = fmaf(hk, cf2[kk], a2f[b]);
                    a2g[b] = fmaf(hk, cg2[kk], a2g[b]);
                    a2o[b] = fmaf(hk, co2[kk], a2o[b]);
                }
            }
        }
    }

    const float wfc_j = Wfc[j];
    const float bfc0  = bfc[0];
    #pragma unroll
    for (int b = 0; b < NBT; b++) {
        float cn  = fmaf(sigf(a2f[b]), c[b], sigf(a2i[b]) * tanhf_fast(a2g[b]));
        float h1f = sigf(a2o[b]) * tanhf_fast(cn);
        float v = h1f * wfc_j;
        #pragma unroll
        for (int m = 16; m > 0; m >>= 1)
            v += __shfl_xor_sync(0xffffffffu, v, m);
        if (j == 0) out[b0 + b] = v + bfc0;
    }
}

// ---------------------------------------------------------------------------
// Kernel: 586 one-warp blocks. Blocks 0..584 scan 7 batches each (585*7=4095);
// block 585 scans the last batch. <=1 warp per SMSP chip-wide: binding SMSP
// carries 462 FFMA2/step (vs 528 at NB=4's 2-warp binding) -> 12.5% lower
// structural floor at identical total work.
// ---------------------------------------------------------------------------
__global__ void __launch_bounds__(32) lstm_kernel(
    const float* __restrict__ x,
    const float* __restrict__ h0,   const float* __restrict__ c0,
    const float* __restrict__ Wih1, const float* __restrict__ Whh1,
    const float* __restrict__ bih1, const float* __restrict__ bhh1,
    const float* __restrict__ Wih2, const float* __restrict__ Whh2,
    const float* __restrict__ bih2, const float* __restrict__ bhh2,
    const float* __restrict__ Wfc,  const float* __restrict__ bfc,
    float* __restrict__ out)
{
    __shared__ __align__(16) u64 Hs[2][NB7][HID];   // 3.5 KB

    if (blockIdx.x < NBLK7) {
        lstm_body<NB7>(blockIdx.x * NB7, Hs, x, h0, c0, Wih1, Whh1, bih1, bhh1,
                       Wih2, Whh2, bih2, bhh2, Wfc, bfc, out);
    } else {
        lstm_body<1>(NBLK7 * NB7, Hs, x, h0, c0, Wih1, Whh1, bih1, bhh1,
                     Wih2, Whh2, bih2, bhh2, Wfc, bfc, out);
    }
}

// ---------------------------------------------------------------------------
// kernel_launch: single fused launch (graph-capturable)
// Input order: x,h0,c0,h1,c1,Wih1,Whh1,bih1,bhh1,Wih2,Whh2,bih2,bhh2,Wfc,bfc
// ---------------------------------------------------------------------------
extern "C" void kernel_launch(void* const* d_in, const int* in_sizes, int n_in,
                              void* d_out, int out_size)
{
    const float* x    = (const float*)d_in[0];
    const float* h0   = (const float*)d_in[1];
    const float* c0   = (const float*)d_in[2];
    const float* Wih1 = (const float*)d_in[5];
    const float* Whh1 = (const float*)d_in[6];
    const float* bih1 = (const float*)d_in[7];
    const float* bhh1 = (const float*)d_in[8];
    const float* Wih2 = (const float*)d_in[9];
    const float* Whh2 = (const float*)d_in[10];
    const float* bih2 = (const float*)d_in[11];
    const float* bhh2 = (const float*)d_in[12];
    const float* Wfc  = (const float*)d_in[13];
    const float* bfc  = (const float*)d_in[14];
    float* out = (float*)d_out;

    lstm_kernel<<<NBLK7 + 1, 32>>>(x, h0, c0, Wih1, Whh1, bih1, bhh1,
                                   Wih2, Whh2, bih2, bhh2, Wfc, bfc, out);
}